// round 4
// baseline (speedup 1.0000x reference)
#include <cuda_runtime.h>
#include <cuda_bf16.h>

#define KDIM  64
#define LOG2E 1.4426950408889634f
#define LN2   0.6931471805599453f
#define WPC   4          // warps (rows) per CTA
#define DIST  4          // prefetch distance (steps)
#define TH    -1000000.0f
#define FULL  0xffffffffu

__device__ __forceinline__ unsigned long long pk2(float a, float b) {
    unsigned long long r;
    asm("mov.b64 %0, {%1, %2};" : "=l"(r) : "f"(a), "f"(b));
    return r;
}
__device__ __forceinline__ unsigned long long fma2(unsigned long long a, unsigned long long b,
                                                   unsigned long long c) {
    unsigned long long d;
    asm("fma.rn.f32x2 %0, %1, %2, %3;" : "=l"(d) : "l"(a), "l"(b), "l"(c));
    return d;
}
__device__ __forceinline__ unsigned long long add2(unsigned long long a, unsigned long long b) {
    unsigned long long d;
    asm("add.rn.f32x2 %0, %1, %2;" : "=l"(d) : "l"(a), "l"(b));
    return d;
}
__device__ __forceinline__ float ex2f(float x) {
    float y; asm("ex2.approx.f32 %0, %1;" : "=f"(y) : "f"(x)); return y;
}
__device__ __forceinline__ float lg2f(float x) {
    float y; asm("lg2.approx.f32 %0, %1;" : "=f"(y) : "f"(x)); return y;
}

// ONE WARP per batch row; lane l owns states (2l, 2l+1).
// Residual w_j(t): sh_e[buf][j] = 2^(w_j(t)); true alpha2_j(t) = C2(t) + w_j(t).
// Step: w_j(t) = lg2( sum_i E[i][j]*2^(w_i(t-1)) ) + emit2 - delta,  delta = w_0(t-1)
// (broadcast via shfl, one step stale => off critical path), C2 += delta.
// Per-step sync is a single __syncwarp; no block barriers in the recursion.
__global__ __launch_bounds__(32 * WPC, 1) void crf_fwd_kernel(
    const float* __restrict__ y_pred,   // [B, N, K]
    const float* __restrict__ trans,    // [K, K]
    const int*   __restrict__ y_true,   // [B, N]
    float*       __restrict__ out,      // [B]
    int N, int B)
{
    __shared__ float sh_trans[KDIM * KDIM];
    __shared__ __align__(16) float sh_e[WPC][2][KDIM];

    const int lane = threadIdx.x & 31;
    const int w    = threadIdx.x >> 5;
    const int row  = blockIdx.x * WPC + w;

    for (int i = threadIdx.x; i < KDIM * KDIM; i += 32 * WPC) sh_trans[i] = trans[i];
    __syncthreads();
    if (row >= B) return;

    const int sa = 2 * lane, sb = 2 * lane + 1;

    // E columns for my two states: Ec[k] pairs rows (2k, 2k+1).
    unsigned long long Eca[KDIM / 2], Ecb[KDIM / 2];
#pragma unroll
    for (int k = 0; k < KDIM / 2; ++k) {
        Eca[k] = pk2(__expf(sh_trans[(2 * k) * KDIM + sa]),
                     __expf(sh_trans[(2 * k + 1) * KDIM + sa]));
        Ecb[k] = pk2(__expf(sh_trans[(2 * k) * KDIM + sb]),
                     __expf(sh_trans[(2 * k + 1) * KDIM + sb]));
    }

    const float* yrow = y_pred + (size_t)row * N * KDIM;
    const int*   trow = y_true + (size_t)row * N;

    // ---- t = 0 ----
    float2 y0 = *(const float2*)(yrow + sa);
    int yt0 = trow[0];
    unsigned m = __all_sync(FULL, (y0.x > TH) && (y0.y > TH));
    float fm = m ? 1.0f : 0.0f;
    float xa = (y0.x * fm) * LOG2E;
    float xb = (y0.y * fm) * LOG2E;
    float point = ((sa == yt0) ? y0.x * fm : 0.0f) + ((sb == yt0) ? y0.y * fm : 0.0f);
    int   prev_yt = yt0;
    float prev_m  = fm;
    float C2 = 0.0f, tv = 0.0f;
    float ea = ex2f(xa), eb = ex2f(xb);
    *(float2*)&sh_e[w][0][sa] = make_float2(ea, eb);
    float delta = __shfl_sync(FULL, xa, 0);

    // ---- prime prefetch ring (steps 1..DIST) ----
    float2 ring[DIST];
    int    tring[DIST];
#pragma unroll
    for (int p = 1; p <= DIST; ++p) {
        int tt = (p < N) ? p : (N - 1);
        ring[p & (DIST - 1)]  = *(const float2*)(yrow + (size_t)tt * KDIM + sa);
        tring[p & (DIST - 1)] = trow[tt];
    }

    // ---- main loop (unroll 4: ring index & buffer parity compile-time) ----
    for (int t0 = 1; t0 < N; t0 += 4) {
#pragma unroll
        for (int u = 0; u < 4; ++u) {
            const int t = t0 + u;
            if (t < N) {
                const int rp   = (1 + u) & (DIST - 1);   // t & 3  (t0 === 1 mod 4)
                const int buf  = (1 + u) & 1;            // t & 1
                const int pbuf = buf ^ 1;

                __syncwarp();                            // prev STS visible to whole warp
                float2 yv = ring[rp];
                int    yt = tring[rp];
                m = __all_sync(FULL, (yv.x > TH) && (yv.y > TH));

                // prefetch t+DIST
                int tt = (t + DIST < N) ? (t + DIST) : (N - 1);
                ring[rp]  = *(const float2*)(yrow + (size_t)tt * KDIM + sa);
                tring[rp] = trow[tt];

                // two dots over shared e-vector: 16 LDS.128 + 64 FFMA2, no repacking
                unsigned long long A0 = 0, A1 = 0, A2 = 0, A3 = 0;
                unsigned long long B0 = 0, B1 = 0, B2 = 0, B3 = 0;
                const ulonglong2* ep = (const ulonglong2*)sh_e[w][pbuf];
#pragma unroll
                for (int k = 0; k < KDIM / 4; ++k) {
                    ulonglong2 ee = ep[k];               // pairs (4k,4k+1) and (4k+2,4k+3)
                    if (k & 1) {
                        A2 = fma2(ee.x, Eca[2 * k], A2); A3 = fma2(ee.y, Eca[2 * k + 1], A3);
                        B2 = fma2(ee.x, Ecb[2 * k], B2); B3 = fma2(ee.y, Ecb[2 * k + 1], B3);
                    } else {
                        A0 = fma2(ee.x, Eca[2 * k], A0); A1 = fma2(ee.y, Eca[2 * k + 1], A1);
                        B0 = fma2(ee.x, Ecb[2 * k], B0); B1 = fma2(ee.y, Ecb[2 * k + 1], B1);
                    }
                }
                unsigned long long AA = add2(add2(A0, A1), add2(A2, A3));
                unsigned long long BB = add2(add2(B0, B1), add2(B2, B3));
                float alo, ahi, blo, bhi;
                asm("mov.b64 {%0, %1}, %2;" : "=f"(alo), "=f"(ahi) : "l"(AA));
                asm("mov.b64 {%0, %1}, %2;" : "=f"(blo), "=f"(bhi) : "l"(BB));
                float sA = alo + ahi;
                float sB = blo + bhi;

                fm = m ? 1.0f : 0.0f;
                float fl2 = fm * LOG2E;
                float xan = lg2f(sA) + yv.x * fl2;
                float xbn = lg2f(sB) + yv.y * fl2;
                xa = (m ? xan : xa) - delta;
                xb = (m ? xbn : xb) - delta;
                C2 += delta;

                point += ((sa == yt) ? yv.x * fm : 0.0f) + ((sb == yt) ? yv.y * fm : 0.0f);
                if (lane == 0) tv += sh_trans[prev_yt * KDIM + yt] * (prev_m * fm);
                prev_yt = yt; prev_m = fm;

                delta = __shfl_sync(FULL, xa, 0);        // for next step (off-chain)
                ea = ex2f(xa); eb = ex2f(xb);
                *(float2*)&sh_e[w][buf][sa] = make_float2(ea, eb);
            }
        }
    }

    // ---- epilogue: warp-reduce 2^(w_i) and point; lane 0 writes ----
    float se = ea + eb;
    float pp = point;
#pragma unroll
    for (int o = 16; o > 0; o >>= 1) {
        se += __shfl_xor_sync(FULL, se, o);
        pp += __shfl_xor_sync(FULL, pp, o);
    }
    if (lane == 0) out[row] = LN2 * (C2 + lg2f(se)) - (pp + tv);
}

extern "C" void kernel_launch(void* const* d_in, const int* in_sizes, int n_in,
                              void* d_out, int out_size) {
    const float* y_pred = (const float*)d_in[0];   // [B, N, K] f32
    const float* trans  = (const float*)d_in[1];   // [K, K]    f32
    const int*   y_true = (const int*)  d_in[2];   // [B, N]    i32
    float* out = (float*)d_out;                    // [B]       f32

    int B = out_size;                  // 512
    int N = in_sizes[2] / B;           // 1024
    int blocks = (B + WPC - 1) / WPC;  // 128
    crf_fwd_kernel<<<blocks, 32 * WPC>>>(y_pred, trans, y_true, out, N, B);
}

// round 5
// speedup vs baseline: 1.6314x; 1.6314x over previous
#include <cuda_runtime.h>
#include <cuda_bf16.h>

#define KDIM  64
#define LOG2E 1.4426950408889634f
#define LN2   0.6931471805599453f
#define WPC   4          // warps (rows) per CTA
#define DIST  4          // emit prefetch distance (steps), power of 2
#define TH    -1000000.0f
#define FULL  0xffffffffu

__device__ __forceinline__ unsigned long long pk2(float a, float b) {
    unsigned long long r;
    asm("mov.b64 %0, {%1, %2};" : "=l"(r) : "f"(a), "f"(b));
    return r;
}
__device__ __forceinline__ unsigned long long fma2(unsigned long long a, unsigned long long b,
                                                   unsigned long long c) {
    unsigned long long d;
    asm("fma.rn.f32x2 %0, %1, %2, %3;" : "=l"(d) : "l"(a), "l"(b), "l"(c));
    return d;
}
__device__ __forceinline__ unsigned long long add2(unsigned long long a, unsigned long long b) {
    unsigned long long d;
    asm("add.rn.f32x2 %0, %1, %2;" : "=l"(d) : "l"(a), "l"(b));
    return d;
}
__device__ __forceinline__ float ex2f(float x) {
    float y; asm("ex2.approx.f32 %0, %1;" : "=f"(y) : "f"(x)); return y;
}
__device__ __forceinline__ float lg2f(float x) {
    float y; asm("lg2.approx.f32 %0, %1;" : "=f"(y) : "f"(x)); return y;
}

// ONE WARP per batch row; lane l owns states (2l, 2l+1).
// Residual w_j(t): sh_e[buf][j] = 2^(w_j(t)); true alpha2_j(t) = C2(t) + w_j(t).
// w_j(t) = lg2( sum_i E[i][j]*2^(w_i(t-1)) ) + emit2 - delta, delta = w_0(t-1) via smem.
// Branch-free steady state: steps t >= N execute as dummy masked steps (m forced 0),
// which only shift the (C2, w) frame -> final result invariant. No interior branches,
// no lane-0 branch (tv is warp-uniform), no shfl; per step: 1 vote (early) + 1 syncwarp.
__global__ __launch_bounds__(32 * WPC, 1) void crf_fwd_kernel(
    const float* __restrict__ y_pred,   // [B, N, K]
    const float* __restrict__ trans,    // [K, K]
    const int*   __restrict__ y_true,   // [B, N]
    float*       __restrict__ out,      // [B]
    int N, int B)
{
    __shared__ float sh_trans[KDIM * KDIM];
    __shared__ __align__(16) float sh_e[WPC][2][KDIM];
    __shared__ float sh_d[WPC][2];

    const int lane = threadIdx.x & 31;
    const int w    = threadIdx.x >> 5;
    const int row  = blockIdx.x * WPC + w;

    for (int i = threadIdx.x; i < KDIM * KDIM; i += 32 * WPC) sh_trans[i] = trans[i];
    __syncthreads();
    if (row >= B) return;

    const int sa = 2 * lane, sb = sa + 1;

    // E columns for my two states: Ec[k] packs rows (2k, 2k+1).
    unsigned long long Eca[KDIM / 2], Ecb[KDIM / 2];
#pragma unroll
    for (int k = 0; k < KDIM / 2; ++k) {
        Eca[k] = pk2(__expf(sh_trans[(2 * k) * KDIM + sa]),
                     __expf(sh_trans[(2 * k + 1) * KDIM + sa]));
        Ecb[k] = pk2(__expf(sh_trans[(2 * k) * KDIM + sb]),
                     __expf(sh_trans[(2 * k + 1) * KDIM + sb]));
    }

    const float* yrow = y_pred + (size_t)row * N * KDIM;
    const int*   trow = y_true + (size_t)row * N;

    // ---- t = 0 ----
    float2 y0 = *(const float2*)(yrow + sa);
    int yt0 = trow[0];
    unsigned m0 = __all_sync(FULL, (y0.x > TH) && (y0.y > TH));
    float fm0 = m0 ? 1.0f : 0.0f;
    float xa = (y0.x * fm0) * LOG2E;
    float xb = (y0.y * fm0) * LOG2E;
    float point = ((sa == yt0) ? y0.x * fm0 : 0.0f) + ((sb == yt0) ? y0.y * fm0 : 0.0f);
    float C2 = 0.0f, tv = 0.0f;
    float ea = ex2f(xa), eb = ex2f(xb);
    *(float2*)&sh_e[w][0][sa] = make_float2(ea, eb);
    if (lane == 0) sh_d[w][0] = xa;
    float fmprev = fm0;

    // ---- prime pipelines ----
    float2 ring[DIST];
#pragma unroll
    for (int p = 1; p <= DIST; ++p) {
        int tt = (p < N) ? p : (N - 1);
        ring[p & (DIST - 1)] = *(const float2*)(yrow + (size_t)tt * KDIM + sa);
    }
    int yt_cur = trow[(1 < N) ? 1 : (N - 1)];
    int yt_nx  = trow[(2 < N) ? 2 : (N - 1)];
    float trv_cur = sh_trans[yt0 * KDIM + yt_cur];
    unsigned mcur = __all_sync(FULL, (ring[1 & (DIST - 1)].x > TH) &&
                                     (ring[1 & (DIST - 1)].y > TH));
    if (1 >= N) mcur = 0u;
    float fmcur = mcur ? 1.0f : 0.0f;

#define STEP(T, RP, RPN, BUF, PBUF)                                                  \
    {                                                                                \
        float2 yv = ring[RP];                                                        \
        int tt = ((T) + DIST < N) ? ((T) + DIST) : (N - 1);                          \
        ring[RP] = *(const float2*)(yrow + (size_t)tt * KDIM + sa);                  \
        unsigned mnext = __all_sync(FULL, (ring[RPN].x > TH) && (ring[RPN].y > TH)); \
        mnext = ((T) + 1 < N) ? mnext : 0u;                                          \
        float fmnext = mnext ? 1.0f : 0.0f;                                          \
        int tn = ((T) + 2 < N) ? ((T) + 2) : (N - 1);                                \
        int yt_nx2 = trow[tn];                                                       \
        float trv_next = sh_trans[yt_cur * KDIM + yt_nx];                            \
        __syncwarp();                                                                \
        float delta = sh_d[w][PBUF];                                                 \
        unsigned long long A0 = 0, A1 = 0, A2 = 0, A3 = 0;                           \
        unsigned long long B0 = 0, B1 = 0, B2 = 0, B3 = 0;                           \
        const ulonglong2* ep = (const ulonglong2*)sh_e[w][PBUF];                     \
        _Pragma("unroll")                                                            \
        for (int k = 0; k < KDIM / 4; ++k) {                                         \
            ulonglong2 ee = ep[k];                                                   \
            if (k & 1) {                                                             \
                A2 = fma2(ee.x, Eca[2 * k], A2); A3 = fma2(ee.y, Eca[2 * k + 1], A3);\
                B2 = fma2(ee.x, Ecb[2 * k], B2); B3 = fma2(ee.y, Ecb[2 * k + 1], B3);\
            } else {                                                                 \
                A0 = fma2(ee.x, Eca[2 * k], A0); A1 = fma2(ee.y, Eca[2 * k + 1], A1);\
                B0 = fma2(ee.x, Ecb[2 * k], B0); B1 = fma2(ee.y, Ecb[2 * k + 1], B1);\
            }                                                                        \
        }                                                                            \
        unsigned long long AA = add2(add2(A0, A1), add2(A2, A3));                    \
        unsigned long long BB = add2(add2(B0, B1), add2(B2, B3));                    \
        float alo, ahi, blo, bhi;                                                    \
        asm("mov.b64 {%0, %1}, %2;" : "=f"(alo), "=f"(ahi) : "l"(AA));               \
        asm("mov.b64 {%0, %1}, %2;" : "=f"(blo), "=f"(bhi) : "l"(BB));               \
        float sA = alo + ahi, sB = blo + bhi;                                        \
        float fl2 = fmcur * LOG2E;                                                   \
        float xan = lg2f(sA) + yv.x * fl2;                                           \
        float xbn = lg2f(sB) + yv.y * fl2;                                           \
        xa = (mcur ? xan : xa) - delta;                                              \
        xb = (mcur ? xbn : xb) - delta;                                              \
        C2 += delta;                                                                 \
        point += ((sa == yt_cur) ? yv.x * fmcur : 0.0f)                              \
               + ((sb == yt_cur) ? yv.y * fmcur : 0.0f);                             \
        tv += trv_cur * (fmprev * fmcur);                                            \
        if (lane == 0) sh_d[w][BUF] = xa;                                            \
        ea = ex2f(xa); eb = ex2f(xb);                                                \
        *(float2*)&sh_e[w][BUF][sa] = make_float2(ea, eb);                           \
        fmprev = fmcur; mcur = mnext; fmcur = fmnext;                                \
        trv_cur = trv_next; yt_cur = yt_nx; yt_nx = yt_nx2;                          \
    }

    // ---- main loop: t0 === 1 (mod 4); overflow steps are harmless dummy steps ----
    for (int t0 = 1; t0 < N; t0 += 4) {
        STEP(t0 + 0, 1, 2, 1, 0)
        STEP(t0 + 1, 2, 3, 0, 1)
        STEP(t0 + 2, 3, 0, 1, 0)
        STEP(t0 + 3, 0, 1, 0, 1)
    }
#undef STEP

    // ---- epilogue: warp-reduce 2^(w_i) and point; tv is warp-uniform ----
    float se = ea + eb;
    float pp = point;
#pragma unroll
    for (int o = 16; o > 0; o >>= 1) {
        se += __shfl_xor_sync(FULL, se, o);
        pp += __shfl_xor_sync(FULL, pp, o);
    }
    if (lane == 0) out[row] = LN2 * (C2 + lg2f(se)) - (pp + tv);
}

extern "C" void kernel_launch(void* const* d_in, const int* in_sizes, int n_in,
                              void* d_out, int out_size) {
    const float* y_pred = (const float*)d_in[0];   // [B, N, K] f32
    const float* trans  = (const float*)d_in[1];   // [K, K]    f32
    const int*   y_true = (const int*)  d_in[2];   // [B, N]    i32
    float* out = (float*)d_out;                    // [B]       f32

    int B = out_size;                  // 512
    int N = in_sizes[2] / B;           // 1024
    int blocks = (B + WPC - 1) / WPC;  // 128
    crf_fwd_kernel<<<blocks, 32 * WPC>>>(y_pred, trans, y_true, out, N, B);
}

// round 6
// speedup vs baseline: 1.8092x; 1.1090x over previous
#include <cuda_runtime.h>
#include <cuda_bf16.h>

#define KDIM  64
#define LOG2E 1.4426950408889634f
#define LN2   0.6931471805599453f
#define WPC   4          // warps (rows) per CTA
#define DIST  4          // emit prefetch distance (steps), power of 2
#define TH    -1000000.0f
#define FULL  0xffffffffu

__device__ __forceinline__ unsigned long long pk2(float a, float b) {
    unsigned long long r;
    asm("mov.b64 %0, {%1, %2};" : "=l"(r) : "f"(a), "f"(b));
    return r;
}
__device__ __forceinline__ unsigned long long fma2(unsigned long long a, unsigned long long b,
                                                   unsigned long long c) {
    unsigned long long d;
    asm("fma.rn.f32x2 %0, %1, %2, %3;" : "=l"(d) : "l"(a), "l"(b), "l"(c));
    return d;
}
__device__ __forceinline__ unsigned long long add2(unsigned long long a, unsigned long long b) {
    unsigned long long d;
    asm("add.rn.f32x2 %0, %1, %2;" : "=l"(d) : "l"(a), "l"(b));
    return d;
}
__device__ __forceinline__ float ex2f(float x) {
    float y; asm("ex2.approx.f32 %0, %1;" : "=f"(y) : "f"(x)); return y;
}
__device__ __forceinline__ float lg2f(float x) {
    float y; asm("lg2.approx.f32 %0, %1;" : "=f"(y) : "f"(x)); return y;
}
// scalb by integer: multiply by 2^(-d) via exponent-field subtract (x > 0, normal)
__device__ __forceinline__ float scalbn_fast(float x, int d) {
    return __int_as_float(__float_as_int(x) - (d << 23));
}

// ONE WARP per batch row; lane l owns states (2l, 2l+1).
// Pure exp-domain recursion, NO per-step lg2/ex2 on the critical path:
//   e_j(t) = [ m_t ? s_j(t) * p_j(t) : e_j(t-1) ] * 2^(-d),
// where s_j = sum_i e_i(t-1) * E[i][j]   (packed-f32x2 FMA dot),
//       p_j = 2^(emit_j * log2 e)        (MUFU, computed EARLY => latency hidden),
//       d   = exponent-bits(e_0(t-1..)) lane-0 renorm, applied as integer exponent
//             subtract; C2i += d exactly (integer). alpha2_j(t) = C2i + lg2(e_j(t)).
// Dummy steps t >= N run masked (m=0): pure frame shift, result invariant.
__global__ __launch_bounds__(32 * WPC, 1) void crf_fwd_kernel(
    const float* __restrict__ y_pred,   // [B, N, K]
    const float* __restrict__ trans,    // [K, K]
    const int*   __restrict__ y_true,   // [B, N]
    float*       __restrict__ out,      // [B]
    int N, int B)
{
    __shared__ float sh_trans[KDIM * KDIM];
    __shared__ __align__(16) float sh_e[WPC][2][KDIM];
    __shared__ int sh_di[WPC][2];

    const int lane = threadIdx.x & 31;
    const int w    = threadIdx.x >> 5;
    const int row  = blockIdx.x * WPC + w;

    for (int i = threadIdx.x; i < KDIM * KDIM; i += 32 * WPC) sh_trans[i] = trans[i];
    __syncthreads();
    if (row >= B) return;

    const int sa = 2 * lane, sb = sa + 1;

    // E columns for my two states: Ec[k] packs rows (2k, 2k+1).
    unsigned long long Eca[KDIM / 2], Ecb[KDIM / 2];
#pragma unroll
    for (int k = 0; k < KDIM / 2; ++k) {
        Eca[k] = pk2(__expf(sh_trans[(2 * k) * KDIM + sa]),
                     __expf(sh_trans[(2 * k + 1) * KDIM + sa]));
        Ecb[k] = pk2(__expf(sh_trans[(2 * k) * KDIM + sb]),
                     __expf(sh_trans[(2 * k + 1) * KDIM + sb]));
    }

    const float* yrow = y_pred + (size_t)row * N * KDIM;
    const int*   trow = y_true + (size_t)row * N;

    // ---- t = 0 ----
    float2 y0 = *(const float2*)(yrow + sa);
    int yt0 = trow[0];
    unsigned m0 = __all_sync(FULL, (y0.x > TH) && (y0.y > TH));
    float fm0 = m0 ? 1.0f : 0.0f;
    float ea = ex2f((y0.x * fm0) * LOG2E);   // e_j(0) = 2^(alpha2_j(0)), C2i = 0
    float eb = ex2f((y0.y * fm0) * LOG2E);
    float point = ((sa == yt0) ? y0.x * fm0 : 0.0f) + ((sb == yt0) ? y0.y * fm0 : 0.0f);
    int   C2i = 0;
    float tv = 0.0f;
    *(float2*)&sh_e[w][0][sa] = make_float2(ea, eb);
    if (lane == 0) sh_di[w][0] = (int)(__float_as_int(ea) >> 23) - 127;
    float fmprev = fm0;

    // ---- prime pipelines ----
    float2 ring[DIST];
#pragma unroll
    for (int p = 1; p <= DIST; ++p) {
        int tt = (p < N) ? p : (N - 1);
        ring[p & (DIST - 1)] = *(const float2*)(yrow + (size_t)tt * KDIM + sa);
    }
    int yt_cur = trow[(1 < N) ? 1 : (N - 1)];
    int yt_nx  = trow[(2 < N) ? 2 : (N - 1)];
    float trv_cur = sh_trans[yt0 * KDIM + yt_cur];
    unsigned mcur = __all_sync(FULL, (ring[1 & (DIST - 1)].x > TH) &&
                                     (ring[1 & (DIST - 1)].y > TH));
    if (1 >= N) mcur = 0u;
    float fmcur = mcur ? 1.0f : 0.0f;

#define STEP(T, RP, RPN, BUF, PBUF)                                                  \
    {                                                                                \
        float2 yv = ring[RP];                                                        \
        int tt = ((T) + DIST < N) ? ((T) + DIST) : (N - 1);                          \
        ring[RP] = *(const float2*)(yrow + (size_t)tt * KDIM + sa);                  \
        unsigned mnext = __all_sync(FULL, (ring[RPN].x > TH) && (ring[RPN].y > TH)); \
        mnext = ((T) + 1 < N) ? mnext : 0u;                                          \
        float fmnext = mnext ? 1.0f : 0.0f;                                          \
        int tn = ((T) + 2 < N) ? ((T) + 2) : (N - 1);                                \
        int yt_nx2 = trow[tn];                                                       \
        float trv_next = sh_trans[yt_cur * KDIM + yt_nx];                            \
        float fl2 = fmcur * LOG2E;                                                   \
        float pa = ex2f(yv.x * fl2);   /* MUFU early: latency hidden by sync+dot */  \
        float pb = ex2f(yv.y * fl2);                                                 \
        __syncwarp();                                                                \
        int d = sh_di[w][PBUF];                                                      \
        unsigned long long A0 = 0, A1 = 0, A2 = 0, A3 = 0;                           \
        unsigned long long B0 = 0, B1 = 0, B2 = 0, B3 = 0;                           \
        const ulonglong2* ep = (const ulonglong2*)sh_e[w][PBUF];                     \
        _Pragma("unroll")                                                            \
        for (int k = 0; k < KDIM / 4; ++k) {                                         \
            ulonglong2 ee = ep[k];                                                   \
            if (k & 1) {                                                             \
                A2 = fma2(ee.x, Eca[2 * k], A2); A3 = fma2(ee.y, Eca[2 * k + 1], A3);\
                B2 = fma2(ee.x, Ecb[2 * k], B2); B3 = fma2(ee.y, Ecb[2 * k + 1], B3);\
            } else {                                                                 \
                A0 = fma2(ee.x, Eca[2 * k], A0); A1 = fma2(ee.y, Eca[2 * k + 1], A1);\
                B0 = fma2(ee.x, Ecb[2 * k], B0); B1 = fma2(ee.y, Ecb[2 * k + 1], B1);\
            }                                                                        \
        }                                                                            \
        unsigned long long AA = add2(add2(A0, A1), add2(A2, A3));                    \
        unsigned long long BB = add2(add2(B0, B1), add2(B2, B3));                    \
        float alo, ahi, blo, bhi;                                                    \
        asm("mov.b64 {%0, %1}, %2;" : "=f"(alo), "=f"(ahi) : "l"(AA));               \
        asm("mov.b64 {%0, %1}, %2;" : "=f"(blo), "=f"(bhi) : "l"(BB));               \
        float qa = mcur ? (alo + ahi) * pa : ea;                                     \
        float qb = mcur ? (blo + bhi) * pb : eb;                                     \
        ea = scalbn_fast(qa, d);                                                     \
        eb = scalbn_fast(qb, d);                                                     \
        C2i += d;                                                                    \
        point += ((sa == yt_cur) ? yv.x * fmcur : 0.0f)                              \
               + ((sb == yt_cur) ? yv.y * fmcur : 0.0f);                             \
        tv += trv_cur * (fmprev * fmcur);                                            \
        if (lane == 0) sh_di[w][BUF] = (int)(__float_as_int(ea) >> 23) - 127;        \
        *(float2*)&sh_e[w][BUF][sa] = make_float2(ea, eb);                           \
        fmprev = fmcur; mcur = mnext; fmcur = fmnext;                                \
        trv_cur = trv_next; yt_cur = yt_nx; yt_nx = yt_nx2;                          \
    }

    // ---- main loop: t0 === 1 (mod 4); overflow steps are harmless dummy steps ----
    for (int t0 = 1; t0 < N; t0 += 4) {
        STEP(t0 + 0, 1, 2, 1, 0)
        STEP(t0 + 1, 2, 3, 0, 1)
        STEP(t0 + 2, 3, 0, 1, 0)
        STEP(t0 + 3, 0, 1, 0, 1)
    }
#undef STEP

    // ---- epilogue: alpha2_j = C2i + lg2(e_j); warp-reduce exp-sum and point ----
    float se = ea + eb;
    float pp = point;
#pragma unroll
    for (int o = 16; o > 0; o >>= 1) {
        se += __shfl_xor_sync(FULL, se, o);
        pp += __shfl_xor_sync(FULL, pp, o);
    }
    if (lane == 0) out[row] = LN2 * ((float)C2i + lg2f(se)) - (pp + tv);
}

extern "C" void kernel_launch(void* const* d_in, const int* in_sizes, int n_in,
                              void* d_out, int out_size) {
    const float* y_pred = (const float*)d_in[0];   // [B, N, K] f32
    const float* trans  = (const float*)d_in[1];   // [K, K]    f32
    const int*   y_true = (const int*)  d_in[2];   // [B, N]    i32
    float* out = (float*)d_out;                    // [B]       f32

    int B = out_size;                  // 512
    int N = in_sizes[2] / B;           // 1024
    int blocks = (B + WPC - 1) / WPC;  // 128
    crf_fwd_kernel<<<blocks, 32 * WPC>>>(y_pred, trans, y_true, out, N, B);
}